// round 13
// baseline (speedup 1.0000x reference)
#include <cuda_runtime.h>

#define AN 76725
#define NC 80
#define CA (AN * NC)
#define CA4 (CA / 4)
#define NTIER 3
#define NSUB 32
#define SUBCAP 128
#define TIERCAP (NSUB * SUBCAP)
#define SKEYN 2048
#define MAXKEEP 200
#define IMGF 640.0f
#define T_A 0.9963f
#define T_B 0.99f
#define T_C 0.97f
#define NT 1024
#define NB 64
#define GPREP 375
#define K1T 512
#define FILL1 160
#define FILLB 148
#define FULLW 0xFFFFFFFFu

// Scratch (device globals; zero-initialized at load, g_cntp re-zeroed by
// scatter_kernel at the end of every call -> deterministic replay state)
__device__ float g_boxes[AN * 4];
__device__ float g_area[AN];
__device__ unsigned long long g_cand[NTIER][NC][TIERCAP];  // sub-sliced keys
__device__ int g_cntp[NSUB][NTIER][NC];                    // privatized counters
__device__ int g_kcnt[NC];
__device__ float4 g_kboxg[NC][MAXKEEP];
__device__ float g_kscg[NC][MAXKEEP];
__device__ int g_kidg[NC][MAXKEEP];

__device__ __forceinline__ void gather_quad(float4 v, int q, int sub) {
    float m = fmaxf(fmaxf(v.x, v.y), fmaxf(v.z, v.w));
    if (m > T_C) {
        int f = q * 4;
        int a = f / NC;        // all 4 scores share the row (NC % 4 == 0)
        int c0 = f - a * NC;   // c0 <= 76, no wrap within the quad
        float sv[4] = {v.x, v.y, v.z, v.w};
        #pragma unroll
        for (int k = 0; k < 4; k++) {
            float s = sv[k];
            if (s > T_C) {
                int c = c0 + k;
                int tier = (s > T_A) ? 0 : ((s > T_B) ? 1 : 2);
                int p = atomicAdd(&g_cntp[sub][tier][c], 1);
                if (p < SUBCAP)
                    g_cand[tier][c][sub * SUBCAP + p] =
                        ((unsigned long long)__float_as_uint(s) << 32) |
                        (unsigned long long)(0xFFFFFFFFu - (unsigned)a);
            }
        }
    }
}

// ---------------------------------------------------------------------------
// K1: blocks [0, GPREP) gather candidates + decode boxes;
//     blocks [GPREP, GPREP+FILL1) fill the first part of the output.
// ---------------------------------------------------------------------------
__global__ __launch_bounds__(K1T) void prep_fill_kernel(
    const float* __restrict__ cls, const float* __restrict__ anchors,
    const float* __restrict__ reg, float4* __restrict__ out4, int split4) {
    int tid = threadIdx.x;

    if (blockIdx.x >= GPREP) {
        // ---- fill part A: [0, split4) ----
        const int ca4 = CA4;
        int stride = FILL1 * K1T;
        for (int i = (blockIdx.x - GPREP) * K1T + tid; i < split4; i += stride) {
            float v = (i >= ca4 && i < 2 * ca4) ? -1.0f : 0.0f;
            out4[i] = make_float4(v, v, v, v);
        }
        return;
    }

    int t = blockIdx.x * K1T + tid;
    int sub = (blockIdx.x * 8 + (tid >> 5)) & (NSUB - 1);

    // decode duty (first AN threads of the prep range)
    if (t < AN) {
        int i = t;
        float a0 = anchors[i * 4 + 0], a1 = anchors[i * 4 + 1];
        float a2 = anchors[i * 4 + 2], a3 = anchors[i * 4 + 3];
        float r0 = reg[i * 4 + 0], r1 = reg[i * 4 + 1];
        float r2 = reg[i * 4 + 2], r3 = reg[i * 4 + 3];
        float aw = a2 - a0, ah = a3 - a1;
        float ax = a0 + 0.5f * aw, ay = a1 + 0.5f * ah;
        float cx = ax + r0 * 0.1f * aw;
        float cy = ay + r1 * 0.1f * ah;
        float w = aw * expf(r2 * 0.2f);
        float h = ah * expf(r3 * 0.2f);
        float x1 = fminf(fmaxf(cx - 0.5f * w, 0.0f), IMGF);
        float y1 = fminf(fmaxf(cy - 0.5f * h, 0.0f), IMGF);
        float x2 = fminf(fmaxf(cx + 0.5f * w, 0.0f), IMGF);
        float y2 = fminf(fmaxf(cy + 0.5f * h, 0.0f), IMGF);
        g_boxes[i * 4 + 0] = x1;
        g_boxes[i * 4 + 1] = y1;
        g_boxes[i * 4 + 2] = x2;
        g_boxes[i * 4 + 3] = y2;
        g_area[i] = (x2 - x1) * (y2 - y1);
    }

    // gather duty: 8 strided float4 loads, batched up-front when in range
    const int stride = GPREP * K1T;
    if (t + 7 * stride < CA4) {
        float4 v[8];
        #pragma unroll
        for (int j = 0; j < 8; j++) v[j] = ((const float4*)cls)[t + j * stride];
        #pragma unroll
        for (int j = 0; j < 8; j++) gather_quad(v[j], t + j * stride, sub);
    } else {
        #pragma unroll
        for (int j = 0; j < 8; j++) {
            int q = t + j * stride;
            if (q < CA4) gather_quad(((const float4*)cls)[q], q, sub);
        }
    }
}

// ---------------------------------------------------------------------------
// K3: flat scatter (1 thread per (class, slot)) + counter reset
// ---------------------------------------------------------------------------
__global__ void scatter_kernel(float* __restrict__ out) {
    int flat = blockIdx.x * blockDim.x + threadIdx.x;
    if (flat < NSUB * NTIER * NC) ((int*)g_cntp)[flat] = 0;
    if (flat >= NC * MAXKEEP) return;
    int c = flat / MAXKEEP;
    int t = flat - c * MAXKEEP;
    if (t >= g_kcnt[c]) return;
    int i = g_kidg[c][t];
    out[c * AN + i] = g_kscg[c][t];
    out[CA + c * AN + i] = (float)c;
    ((float4*)(out + 2 * CA))[c * AN + i] = g_kboxg[c][t];
    out[6 * CA + c * AN + i] = 1.0f;
}

// ---------------------------------------------------------------------------
// K2: blocks [0, NC) per-class NMS; blocks [NC, NC+FILLB) fill [split4, n4).
// ---------------------------------------------------------------------------
__global__ __launch_bounds__(NT) void fused_kernel(const float* __restrict__ cls,
                                                   float4* __restrict__ out4,
                                                   int split4, int n4) {
    // ---------------- fill part B ----------------
    if (blockIdx.x >= NC) {
        int fb = blockIdx.x - NC;
        const int ca4 = CA4;
        int stride = FILLB * NT;
        for (int i = split4 + fb * NT + threadIdx.x; i < n4; i += stride) {
            float v = (i >= ca4 && i < 2 * ca4) ? -1.0f : 0.0f;
            out4[i] = make_float4(v, v, v, v);
        }
        return;
    }

    // ---------------- NMS path ----------------
    const int c = blockIdx.x;
    const int tid = threadIdx.x;
    const int lane = tid & 31, wid = tid >> 5;

    __shared__ unsigned long long skey[SKEYN];      // 16KB (fallback: supp bitmap)
    __shared__ unsigned long long cmask64[NB];
    __shared__ float4 bbox[NB];
    __shared__ float bar_[NB], bsc[NB];
    __shared__ int bidx[NB];
    __shared__ float4 kbox[MAXKEEP];
    __shared__ float kar[MAXKEEP], ksc[MAXKEEP];
    __shared__ int kid[MAXKEEP];
    __shared__ unsigned confParts[32];
    __shared__ unsigned long long alive64_s, km64_s;
    __shared__ unsigned long long red32[32];
    __shared__ int kcount;

    unsigned* cmW = (unsigned*)cmask64;
    unsigned* kmW = (unsigned*)&km64_s;

    if (tid == 0) kcount = 0;
    __syncthreads();

    bool ok = true;
    for (int tier = 0; tier < NTIER; tier++) {
        if (kcount >= MAXKEEP) break;

        // concatenate the 32 sub-lists for this (tier, class)
        int n = 0;
        bool of = false;
        for (int s2 = 0; s2 < NSUB; s2++) {
            int cs = g_cntp[s2][tier][c];
            if (cs > SUBCAP) of = true;
            cs = min(cs, SUBCAP);
            for (int i = tid; i < cs; i += NT)
                skey[min(n + i, SKEYN - 1)] = g_cand[tier][c][s2 * SUBCAP + i];
            n += cs;
        }
        if (of || n > SKEYN) { ok = false; break; }
        if (n == 0) continue;

        // ---- pad + bitonic sort descending ----
        int m = 1;
        while (m < n) m <<= 1;
        for (int i = n + tid; i < m; i += NT) skey[i] = 0ULL;
        __syncthreads();
        for (int k = 2; k <= m; k <<= 1) {
            for (int j = k >> 1; j > 0; j >>= 1) {
                for (int i = tid; i < m; i += NT) {
                    int ixj = i ^ j;
                    if (ixj > i) {
                        bool desc = ((i & k) == 0);
                        unsigned long long A = skey[i], B2 = skey[ixj];
                        if (desc ? (A < B2) : (A > B2)) { skey[i] = B2; skey[ixj] = A; }
                    }
                }
                __syncthreads();
            }
        }

        // ---- batched walk, NB=64 ----
        for (int base = 0; base < n; base += NB) {
            if (kcount >= MAXKEEP) break;
            int nb = min(NB, n - base);

            if (tid < nb) {
                unsigned long long key = skey[base + tid];
                float s = __uint_as_float((unsigned)(key >> 32));
                int idx = (int)(0xFFFFFFFFu - (unsigned)key);
                float4 bb;
                bb.x = g_boxes[idx * 4 + 0];
                bb.y = g_boxes[idx * 4 + 1];
                bb.z = g_boxes[idx * 4 + 2];
                bb.w = g_boxes[idx * 4 + 3];
                bbox[tid] = bb;
                bar_[tid] = g_area[idx];
                bsc[tid] = s;
                bidx[tid] = idx;
            }
            __syncthreads();

            int i = tid & 63;
            int g = tid >> 6;  // 0..15
            bool have = i < nb;
            float4 mb = make_float4(0, 0, 0, 0);
            float ma = 0;
            if (have) { mb = bbox[i]; ma = bar_[i]; }

            // phase 1a: conflict vs kept list, 16-way split per candidate
            int kc = kcount;
            bool cfk = false;
            if (have) {
                for (int j = g; j < kc; j += 16) {
                    float4 kb = kbox[j];
                    float ix1 = fmaxf(kb.x, mb.x), iy1 = fmaxf(kb.y, mb.y);
                    float ix2 = fminf(kb.z, mb.z), iy2 = fminf(kb.w, mb.w);
                    float inter = fmaxf(ix2 - ix1, 0.0f) * fmaxf(iy2 - iy1, 0.0f);
                    if (inter > 0.0f) {
                        float iou = inter / ((kar[j] + ma) - inter);
                        if (iou > 0.5f) { cfk = true; break; }
                    }
                }
            }
            unsigned cb = __ballot_sync(FULLW, cfk);
            if (lane == 0) confParts[wid] = cb;
            __syncthreads();
            if (tid == 0) {
                unsigned lo = 0, hi2 = 0;
                #pragma unroll
                for (int w = 0; w < 32; w += 2) { lo |= confParts[w]; hi2 |= confParts[w + 1]; }
                unsigned long long conf = ((unsigned long long)hi2 << 32) | lo;
                unsigned long long hv = (nb >= 64) ? ~0ULL : ((1ULL << nb) - 1ULL);
                alive64_s = hv & ~conf;
            }
            __syncthreads();
            unsigned long long alive64 = alive64_s;

            // phase 1b: conflict matrix, 16 columns per ballot round
            for (int jb = 0; jb < nb; jb += 16) {
                int j = jb + g;
                bool cf = false;
                if (have && j < nb && i != j) {
                    float4 jb4 = bbox[j];
                    float ja = bar_[j];
                    float ix1 = fmaxf(jb4.x, mb.x), iy1 = fmaxf(jb4.y, mb.y);
                    float ix2 = fminf(jb4.z, mb.z), iy2 = fminf(jb4.w, mb.w);
                    float inter = fmaxf(ix2 - ix1, 0.0f) * fmaxf(iy2 - iy1, 0.0f);
                    if (inter > 0.0f) {
                        float iou = inter / ((ja + ma) - inter);
                        cf = iou > 0.5f;
                    }
                }
                unsigned bits = __ballot_sync(FULLW, cf);
                if (lane == 0 && j < nb) cmW[2 * j + (wid & 1)] = bits;
            }
            __syncthreads();

            // classify trivial/deferred (threads 0..63)
            {
                bool trivial = false, deferred = false;
                if (tid < 64) {
                    if ((alive64 >> tid) & 1ULL) {
                        unsigned long long below = (1ULL << tid) - 1ULL;
                        unsigned long long conf = cmask64[tid] & alive64 & below;
                        trivial = (conf == 0ULL);
                        deferred = !trivial;
                    }
                }
                unsigned tb = __ballot_sync(FULLW, trivial);
                unsigned db = __ballot_sync(FULLW, deferred);
                if (lane == 0 && wid < 2) kmW[wid] = tb;
                if (lane == 1 && wid < 2) red32[wid] = db;
            }
            __syncthreads();

            // thread 0: resolve deferred serially, truncate to rem
            if (tid == 0) {
                unsigned long long kw = km64_s;
                unsigned long long dbits = ((unsigned long long)(unsigned)red32[1] << 32) |
                                           (unsigned)red32[0];
                while (dbits) {
                    int q = __ffsll((long long)dbits) - 1;
                    dbits &= dbits - 1ULL;
                    unsigned long long below = (1ULL << q) - 1ULL;
                    if ((cmask64[q] & kw & below) == 0ULL) kw |= (1ULL << q);
                }
                int rem = MAXKEEP - kcount;
                int p = __popcll(kw);
                while (p > rem) {
                    kw &= ~(0x8000000000000000ULL >> __clzll((long long)kw));
                    p--;
                }
                km64_s = kw;
            }
            __syncthreads();

            unsigned long long kw = km64_s;
            int kc0 = kcount;
            if (tid < 64 && ((kw >> tid) & 1ULL)) {
                int pos = kc0 + __popcll(kw & ((1ULL << tid) - 1ULL));
                kbox[pos] = bbox[tid];
                kar[pos] = bar_[tid];
                ksc[pos] = bsc[tid];
                kid[pos] = bidx[tid];
            }
            __syncthreads();
            if (tid == 0) kcount = kc0 + __popcll(kw);
            __syncthreads();
        }
    }
    __syncthreads();

    // ---- Exact fallback (never triggered for this data) ----
    if (!ok || kcount < MAXKEEP) {
        unsigned* supp = (unsigned*)skey;
        const int NW = (AN + 31) / 32;
        for (int w2 = tid; w2 < NW; w2 += NT) supp[w2] = 0u;
        if (tid == 0) kcount = 0;
        __syncthreads();
        for (int it = 0; it < MAXKEEP; it++) {
            unsigned long long best = 0ULL;
            for (int i = tid; i < AN; i += NT) {
                if (!((supp[i >> 5] >> (i & 31)) & 1u)) {
                    float s = cls[i * NC + c];
                    if (s > 0.1f) {
                        unsigned long long k =
                            ((unsigned long long)__float_as_uint(s) << 32) |
                            (unsigned long long)(0xFFFFFFFFu - (unsigned)i);
                        if (k > best) best = k;
                    }
                }
            }
            #pragma unroll
            for (int off = 16; off > 0; off >>= 1) {
                unsigned long long o = __shfl_down_sync(FULLW, best, off);
                if (o > best) best = o;
            }
            if (lane == 0) red32[wid] = best;
            __syncthreads();
            if (tid == 0) {
                unsigned long long b2 = red32[0];
                for (int w = 1; w < 32; w++)
                    if (red32[w] > b2) b2 = red32[w];
                red32[0] = b2;
            }
            __syncthreads();
            unsigned long long bk = red32[0];
            __syncthreads();
            if (bk == 0ULL) break;
            int bi = (int)(0xFFFFFFFFu - (unsigned)bk);
            float s = __uint_as_float((unsigned)(bk >> 32));
            float zx1 = g_boxes[bi * 4 + 0], zy1 = g_boxes[bi * 4 + 1];
            float zx2 = g_boxes[bi * 4 + 2], zy2 = g_boxes[bi * 4 + 3];
            float za = g_area[bi];
            if (tid == 0) {
                int kc2 = kcount;
                kbox[kc2] = make_float4(zx1, zy1, zx2, zy2);
                kar[kc2] = za; ksc[kc2] = s; kid[kc2] = bi;
                kcount = kc2 + 1;
            }
            for (int i = tid; i < AN; i += NT) {
                float ix1 = fmaxf(zx1, g_boxes[i * 4 + 0]);
                float iy1 = fmaxf(zy1, g_boxes[i * 4 + 1]);
                float ix2 = fminf(zx2, g_boxes[i * 4 + 2]);
                float iy2 = fminf(zy2, g_boxes[i * 4 + 3]);
                float inter = fmaxf(ix2 - ix1, 0.0f) * fmaxf(iy2 - iy1, 0.0f);
                float iou = inter / ((za + g_area[i]) - inter);
                if (iou > 0.5f || i == bi) atomicOr(&supp[i >> 5], 1u << (i & 31));
            }
            __syncthreads();
        }
        __syncthreads();
    }

    // ---- write compact results to device globals ----
    int kc = kcount;
    if (tid == 0) g_kcnt[c] = kc;
    for (int t = tid; t < kc; t += NT) {
        g_kboxg[c][t] = kbox[t];
        g_kscg[c][t] = ksc[t];
        g_kidg[c][t] = kid[t];
    }
}

// ---------------------------------------------------------------------------
extern "C" void kernel_launch(void* const* d_in, const int* in_sizes, int n_in,
                              void* d_out, int out_size) {
    const float* classification = (const float*)d_in[0];  // [1, A, C]
    const float* regression = (const float*)d_in[1];      // [1, A, 4]
    const float* anchors = (const float*)d_in[2];         // [A, 4]
    float* out = (float*)d_out;

    int n4 = out_size / 4;
    int split4 = n4 / 4;  // 25% of the fill in K1, 75% in K2

    prep_fill_kernel<<<GPREP + FILL1, K1T>>>(classification, anchors, regression,
                                             (float4*)out, split4);
    fused_kernel<<<NC + FILLB, NT>>>(classification, (float4*)out, split4, n4);
    scatter_kernel<<<(NC * MAXKEEP + 255) / 256, 256>>>(out);
}

// round 14
// speedup vs baseline: 1.1029x; 1.1029x over previous
#include <cuda_runtime.h>

#define AN 76725
#define NC 80
#define CA (AN * NC)
#define CA4 (CA / 4)
#define NTIER 3
#define NSUB 32
#define SUBCAP 128
#define TIERCAP (NSUB * SUBCAP)
#define SKEYN 2048
#define MAXKEEP 200
#define IMGF 640.0f
#define T_A 0.9963f
#define T_B 0.99f
#define T_C 0.97f
#define NT 1024
#define NB 64
#define GPREP 1499
#define FILLA 444
#define FILLB 148
#define FULLW 0xFFFFFFFFu

// Scratch (device globals; zero-initialized at load, g_cntp re-zeroed by
// scatter_kernel at the end of every call -> deterministic replay state)
__device__ float g_boxes[AN * 4];
__device__ float g_area[AN];
__device__ unsigned long long g_cand[NTIER][NC][TIERCAP];  // sub-sliced keys
__device__ int g_cntp[NSUB][NTIER][NC];                    // privatized counters
__device__ int g_kcnt[NC];
__device__ float4 g_kboxg[NC][MAXKEEP];
__device__ float g_kscg[NC][MAXKEEP];
__device__ int g_kidg[NC][MAXKEEP];

// ---------------------------------------------------------------------------
// K1: blocks [0, GPREP) = R11-shaped gather + decode (proven 20us config).
//     blocks [GPREP, GPREP+FILLA) = fill of out4[0, split4).
// ---------------------------------------------------------------------------
__global__ __launch_bounds__(256) void prep_kernel(const float* __restrict__ cls,
                                                   const float* __restrict__ anchors,
                                                   const float* __restrict__ reg,
                                                   float4* __restrict__ out4,
                                                   int split4) {
    if (blockIdx.x >= GPREP) {
        // ---- fill part A ----
        const int ca4 = CA4;
        int stride = FILLA * 256;
        for (int i = (blockIdx.x - GPREP) * 256 + threadIdx.x; i < split4; i += stride) {
            float v = (i >= ca4 && i < 2 * ca4) ? -1.0f : 0.0f;
            out4[i] = make_float4(v, v, v, v);
        }
        return;
    }

    int t = blockIdx.x * blockDim.x + threadIdx.x;
    int stride = GPREP * 256;
    int sub = (blockIdx.x * 8 + (threadIdx.x >> 5)) & (NSUB - 1);

    // decode duty for the first AN threads
    if (t < AN) {
        int i = t;
        float a0 = anchors[i * 4 + 0], a1 = anchors[i * 4 + 1];
        float a2 = anchors[i * 4 + 2], a3 = anchors[i * 4 + 3];
        float r0 = reg[i * 4 + 0], r1 = reg[i * 4 + 1];
        float r2 = reg[i * 4 + 2], r3 = reg[i * 4 + 3];
        float aw = a2 - a0, ah = a3 - a1;
        float ax = a0 + 0.5f * aw, ay = a1 + 0.5f * ah;
        float cx = ax + r0 * 0.1f * aw;
        float cy = ay + r1 * 0.1f * ah;
        float w = aw * expf(r2 * 0.2f);
        float h = ah * expf(r3 * 0.2f);
        float x1 = fminf(fmaxf(cx - 0.5f * w, 0.0f), IMGF);
        float y1 = fminf(fmaxf(cy - 0.5f * h, 0.0f), IMGF);
        float x2 = fminf(fmaxf(cx + 0.5f * w, 0.0f), IMGF);
        float y2 = fminf(fmaxf(cy + 0.5f * h, 0.0f), IMGF);
        g_boxes[i * 4 + 0] = x1;
        g_boxes[i * 4 + 1] = y1;
        g_boxes[i * 4 + 2] = x2;
        g_boxes[i * 4 + 3] = y2;
        g_area[i] = (x2 - x1) * (y2 - y1);
    }

    // gather duty: 4 independent float4 loads (MLP), coalesced per iteration
    #pragma unroll
    for (int jj = 0; jj < 4; jj++) {
        int q = t + jj * stride;
        if (q < CA4) {
            float4 v = ((const float4*)cls)[q];
            float sv[4] = {v.x, v.y, v.z, v.w};
            #pragma unroll
            for (int k = 0; k < 4; k++) {
                float s = sv[k];
                if (s > T_C) {
                    int f = q * 4 + k;
                    int c = f % NC;
                    int a = f / NC;
                    int tier = (s > T_A) ? 0 : ((s > T_B) ? 1 : 2);
                    int p = atomicAdd(&g_cntp[sub][tier][c], 1);
                    if (p < SUBCAP)
                        g_cand[tier][c][sub * SUBCAP + p] =
                            ((unsigned long long)__float_as_uint(s) << 32) |
                            (unsigned long long)(0xFFFFFFFFu - (unsigned)a);
                }
            }
        }
    }
}

// ---------------------------------------------------------------------------
// K3: flat scatter (1 thread per (class, slot)) + counter reset
// ---------------------------------------------------------------------------
__global__ void scatter_kernel(float* __restrict__ out) {
    int flat = blockIdx.x * blockDim.x + threadIdx.x;
    if (flat < NSUB * NTIER * NC) ((int*)g_cntp)[flat] = 0;
    if (flat >= NC * MAXKEEP) return;
    int c = flat / MAXKEEP;
    int t = flat - c * MAXKEEP;
    if (t >= g_kcnt[c]) return;
    int i = g_kidg[c][t];
    out[c * AN + i] = g_kscg[c][t];
    out[CA + c * AN + i] = (float)c;
    ((float4*)(out + 2 * CA))[c * AN + i] = g_kboxg[c][t];
    out[6 * CA + c * AN + i] = 1.0f;
}

// ---------------------------------------------------------------------------
// K2: blocks [0, NC) per-class NMS; blocks [NC, NC+FILLB) fill [split4, n4).
// ---------------------------------------------------------------------------
__global__ __launch_bounds__(NT) void fused_kernel(const float* __restrict__ cls,
                                                   float4* __restrict__ out4,
                                                   int split4, int n4) {
    // ---------------- fill part B ----------------
    if (blockIdx.x >= NC) {
        int fb = blockIdx.x - NC;
        const int ca4 = CA4;
        int stride = FILLB * NT;
        for (int i = split4 + fb * NT + threadIdx.x; i < n4; i += stride) {
            float v = (i >= ca4 && i < 2 * ca4) ? -1.0f : 0.0f;
            out4[i] = make_float4(v, v, v, v);
        }
        return;
    }

    // ---------------- NMS path ----------------
    const int c = blockIdx.x;
    const int tid = threadIdx.x;
    const int lane = tid & 31, wid = tid >> 5;

    __shared__ unsigned long long skey[SKEYN];      // 16KB (fallback: supp bitmap)
    __shared__ unsigned long long cmask64[NB];
    __shared__ float4 bbox[NB];
    __shared__ float bar_[NB], bsc[NB];
    __shared__ int bidx[NB];
    __shared__ float4 kbox[MAXKEEP];
    __shared__ float kar[MAXKEEP], ksc[MAXKEEP];
    __shared__ int kid[MAXKEEP];
    __shared__ unsigned confParts[32];
    __shared__ unsigned long long alive64_s, km64_s;
    __shared__ unsigned long long red32[32];
    __shared__ int kcount;
    __shared__ int s_cnts[NTIER][NSUB];   // parallel-preloaded sub-counts

    unsigned* cmW = (unsigned*)cmask64;
    unsigned* kmW = (unsigned*)&km64_s;

    // preload all 96 sub-counts in one parallel burst (kills the serial
    // global-latency chain the old concat loop paid per sub-list)
    if (tid < NSUB * NTIER) {
        int s2 = tid / NTIER, tr = tid - s2 * NTIER;
        s_cnts[tr][s2] = g_cntp[s2][tr][c];
    }
    if (tid == 0) kcount = 0;
    __syncthreads();

    bool ok = true;
    for (int tier = 0; tier < NTIER; tier++) {
        if (kcount >= MAXKEEP) break;

        // concatenate the 32 sub-lists (counts now in shared; loads pipeline)
        int n = 0;
        bool of = false;
        for (int s2 = 0; s2 < NSUB; s2++) {
            int cs = s_cnts[tier][s2];
            if (cs > SUBCAP) of = true;
            cs = min(cs, SUBCAP);
            for (int i = tid; i < cs; i += NT)
                skey[min(n + i, SKEYN - 1)] = g_cand[tier][c][s2 * SUBCAP + i];
            n += cs;
        }
        if (of || n > SKEYN) { ok = false; break; }
        if (n == 0) continue;

        // ---- pad + bitonic sort descending ----
        int m = 1;
        while (m < n) m <<= 1;
        for (int i = n + tid; i < m; i += NT) skey[i] = 0ULL;
        __syncthreads();
        for (int k = 2; k <= m; k <<= 1) {
            for (int j = k >> 1; j > 0; j >>= 1) {
                for (int i = tid; i < m; i += NT) {
                    int ixj = i ^ j;
                    if (ixj > i) {
                        bool desc = ((i & k) == 0);
                        unsigned long long A = skey[i], B2 = skey[ixj];
                        if (desc ? (A < B2) : (A > B2)) { skey[i] = B2; skey[ixj] = A; }
                    }
                }
                __syncthreads();
            }
        }

        // ---- batched walk, NB=64 ----
        for (int base = 0; base < n; base += NB) {
            if (kcount >= MAXKEEP) break;
            int nb = min(NB, n - base);

            if (tid < nb) {
                unsigned long long key = skey[base + tid];
                float s = __uint_as_float((unsigned)(key >> 32));
                int idx = (int)(0xFFFFFFFFu - (unsigned)key);
                float4 bb;
                bb.x = g_boxes[idx * 4 + 0];
                bb.y = g_boxes[idx * 4 + 1];
                bb.z = g_boxes[idx * 4 + 2];
                bb.w = g_boxes[idx * 4 + 3];
                bbox[tid] = bb;
                bar_[tid] = g_area[idx];
                bsc[tid] = s;
                bidx[tid] = idx;
            }
            __syncthreads();

            int i = tid & 63;
            int g = tid >> 6;  // 0..15
            bool have = i < nb;
            float4 mb = make_float4(0, 0, 0, 0);
            float ma = 0;
            if (have) { mb = bbox[i]; ma = bar_[i]; }

            // phase 1a: conflict vs kept list, 16-way split per candidate
            int kc = kcount;
            bool cfk = false;
            if (have) {
                for (int j = g; j < kc; j += 16) {
                    float4 kb = kbox[j];
                    float ix1 = fmaxf(kb.x, mb.x), iy1 = fmaxf(kb.y, mb.y);
                    float ix2 = fminf(kb.z, mb.z), iy2 = fminf(kb.w, mb.w);
                    float inter = fmaxf(ix2 - ix1, 0.0f) * fmaxf(iy2 - iy1, 0.0f);
                    if (inter > 0.0f) {
                        float iou = inter / ((kar[j] + ma) - inter);
                        if (iou > 0.5f) { cfk = true; break; }
                    }
                }
            }
            unsigned cb = __ballot_sync(FULLW, cfk);
            if (lane == 0) confParts[wid] = cb;
            __syncthreads();
            if (tid == 0) {
                unsigned lo = 0, hi2 = 0;
                #pragma unroll
                for (int w = 0; w < 32; w += 2) { lo |= confParts[w]; hi2 |= confParts[w + 1]; }
                unsigned long long conf = ((unsigned long long)hi2 << 32) | lo;
                unsigned long long hv = (nb >= 64) ? ~0ULL : ((1ULL << nb) - 1ULL);
                alive64_s = hv & ~conf;
            }
            __syncthreads();
            unsigned long long alive64 = alive64_s;

            // phase 1b: conflict matrix, 16 columns per ballot round
            for (int jb = 0; jb < nb; jb += 16) {
                int j = jb + g;
                bool cf = false;
                if (have && j < nb && i != j) {
                    float4 jb4 = bbox[j];
                    float ja = bar_[j];
                    float ix1 = fmaxf(jb4.x, mb.x), iy1 = fmaxf(jb4.y, mb.y);
                    float ix2 = fminf(jb4.z, mb.z), iy2 = fminf(jb4.w, mb.w);
                    float inter = fmaxf(ix2 - ix1, 0.0f) * fmaxf(iy2 - iy1, 0.0f);
                    if (inter > 0.0f) {
                        float iou = inter / ((ja + ma) - inter);
                        cf = iou > 0.5f;
                    }
                }
                unsigned bits = __ballot_sync(FULLW, cf);
                if (lane == 0 && j < nb) cmW[2 * j + (wid & 1)] = bits;
            }
            __syncthreads();

            // classify trivial/deferred (threads 0..63)
            {
                bool trivial = false, deferred = false;
                if (tid < 64) {
                    if ((alive64 >> tid) & 1ULL) {
                        unsigned long long below = (1ULL << tid) - 1ULL;
                        unsigned long long conf = cmask64[tid] & alive64 & below;
                        trivial = (conf == 0ULL);
                        deferred = !trivial;
                    }
                }
                unsigned tb = __ballot_sync(FULLW, trivial);
                unsigned db = __ballot_sync(FULLW, deferred);
                if (lane == 0 && wid < 2) kmW[wid] = tb;
                if (lane == 1 && wid < 2) red32[wid] = db;
            }
            __syncthreads();

            // thread 0: resolve deferred serially, truncate to rem
            if (tid == 0) {
                unsigned long long kw = km64_s;
                unsigned long long dbits = ((unsigned long long)(unsigned)red32[1] << 32) |
                                           (unsigned)red32[0];
                while (dbits) {
                    int q = __ffsll((long long)dbits) - 1;
                    dbits &= dbits - 1ULL;
                    unsigned long long below = (1ULL << q) - 1ULL;
                    if ((cmask64[q] & kw & below) == 0ULL) kw |= (1ULL << q);
                }
                int rem = MAXKEEP - kcount;
                int p = __popcll(kw);
                while (p > rem) {
                    kw &= ~(0x8000000000000000ULL >> __clzll((long long)kw));
                    p--;
                }
                km64_s = kw;
            }
            __syncthreads();

            unsigned long long kw = km64_s;
            int kc0 = kcount;
            if (tid < 64 && ((kw >> tid) & 1ULL)) {
                int pos = kc0 + __popcll(kw & ((1ULL << tid) - 1ULL));
                kbox[pos] = bbox[tid];
                kar[pos] = bar_[tid];
                ksc[pos] = bsc[tid];
                kid[pos] = bidx[tid];
            }
            __syncthreads();
            if (tid == 0) kcount = kc0 + __popcll(kw);
            __syncthreads();
        }
    }
    __syncthreads();

    // ---- Exact fallback (never triggered for this data) ----
    if (!ok || kcount < MAXKEEP) {
        unsigned* supp = (unsigned*)skey;
        const int NW = (AN + 31) / 32;
        for (int w2 = tid; w2 < NW; w2 += NT) supp[w2] = 0u;
        if (tid == 0) kcount = 0;
        __syncthreads();
        for (int it = 0; it < MAXKEEP; it++) {
            unsigned long long best = 0ULL;
            for (int i = tid; i < AN; i += NT) {
                if (!((supp[i >> 5] >> (i & 31)) & 1u)) {
                    float s = cls[i * NC + c];
                    if (s > 0.1f) {
                        unsigned long long k =
                            ((unsigned long long)__float_as_uint(s) << 32) |
                            (unsigned long long)(0xFFFFFFFFu - (unsigned)i);
                        if (k > best) best = k;
                    }
                }
            }
            #pragma unroll
            for (int off = 16; off > 0; off >>= 1) {
                unsigned long long o = __shfl_down_sync(FULLW, best, off);
                if (o > best) best = o;
            }
            if (lane == 0) red32[wid] = best;
            __syncthreads();
            if (tid == 0) {
                unsigned long long b2 = red32[0];
                for (int w = 1; w < 32; w++)
                    if (red32[w] > b2) b2 = red32[w];
                red32[0] = b2;
            }
            __syncthreads();
            unsigned long long bk = red32[0];
            __syncthreads();
            if (bk == 0ULL) break;
            int bi = (int)(0xFFFFFFFFu - (unsigned)bk);
            float s = __uint_as_float((unsigned)(bk >> 32));
            float zx1 = g_boxes[bi * 4 + 0], zy1 = g_boxes[bi * 4 + 1];
            float zx2 = g_boxes[bi * 4 + 2], zy2 = g_boxes[bi * 4 + 3];
            float za = g_area[bi];
            if (tid == 0) {
                int kc2 = kcount;
                kbox[kc2] = make_float4(zx1, zy1, zx2, zy2);
                kar[kc2] = za; ksc[kc2] = s; kid[kc2] = bi;
                kcount = kc2 + 1;
            }
            for (int i = tid; i < AN; i += NT) {
                float ix1 = fmaxf(zx1, g_boxes[i * 4 + 0]);
                float iy1 = fmaxf(zy1, g_boxes[i * 4 + 1]);
                float ix2 = fminf(zx2, g_boxes[i * 4 + 2]);
                float iy2 = fminf(zy2, g_boxes[i * 4 + 3]);
                float inter = fmaxf(ix2 - ix1, 0.0f) * fmaxf(iy2 - iy1, 0.0f);
                float iou = inter / ((za + g_area[i]) - inter);
                if (iou > 0.5f || i == bi) atomicOr(&supp[i >> 5], 1u << (i & 31));
            }
            __syncthreads();
        }
        __syncthreads();
    }

    // ---- write compact results to device globals ----
    int kc = kcount;
    if (tid == 0) g_kcnt[c] = kc;
    for (int t = tid; t < kc; t += NT) {
        g_kboxg[c][t] = kbox[t];
        g_kscg[c][t] = ksc[t];
        g_kidg[c][t] = kid[t];
    }
}

// ---------------------------------------------------------------------------
extern "C" void kernel_launch(void* const* d_in, const int* in_sizes, int n_in,
                              void* d_out, int out_size) {
    const float* classification = (const float*)d_in[0];  // [1, A, C]
    const float* regression = (const float*)d_in[1];      // [1, A, 4]
    const float* anchors = (const float*)d_in[2];         // [A, 4]
    float* out = (float*)d_out;

    int n4 = out_size / 4;
    int split4 = (int)(((long long)n4 * 3) / 10);  // 30% of fill in K1

    prep_kernel<<<GPREP + FILLA, 256>>>(classification, anchors, regression,
                                        (float4*)out, split4);
    fused_kernel<<<NC + FILLB, NT>>>(classification, (float4*)out, split4, n4);
    scatter_kernel<<<(NC * MAXKEEP + 255) / 256, 256>>>(out);
}

// round 15
// speedup vs baseline: 1.1645x; 1.0559x over previous
#include <cuda_runtime.h>

#define AN 76725
#define NC 80
#define CA (AN * NC)
#define CA4 (CA / 4)
#define NTIER 3
#define NSUB 32
#define SUBCAP 128
#define TIERCAP (NSUB * SUBCAP)
#define SKEYN 2048
#define MAXKEEP 200
#define IMGF 640.0f
#define T_A 0.9963f
#define T_B 0.99f
#define T_C 0.97f
#define NT 1024
#define NB 64
#define GPREP 1499
#define FILLB 68
#define CH1 (256 * 16)   /* K1 fill chunk: 256 thr x 16 float4 */
#define CH2 (NT * 16)    /* K2 fill chunk: 1024 thr x 16 float4 */
#define FULLW 0xFFFFFFFFu

// Scratch (device globals; zero-initialized at load, counters/cursors
// re-zeroed by scatter_kernel at the end of every call)
__device__ float g_boxes[AN * 4];
__device__ float g_area[AN];
__device__ unsigned long long g_cand[NTIER][NC][TIERCAP];
__device__ int g_cntp[NSUB][NTIER][NC];
__device__ int g_fillcurA, g_fillcurB;
__device__ int g_kcnt[NC];
__device__ float4 g_kboxg[NC][MAXKEEP];
__device__ float g_kscg[NC][MAXKEEP];
__device__ int g_kidg[NC][MAXKEEP];

__device__ __forceinline__ float4 fill_val4(int i) {
    float v = (i >= CA4 && i < 2 * CA4) ? -1.0f : 0.0f;
    return make_float4(v, v, v, v);
}

// ---------------------------------------------------------------------------
// K1: gather + decode (R11-proven shape), then blocks join fill-A via cursor.
// ---------------------------------------------------------------------------
__global__ __launch_bounds__(256) void prep_kernel(const float* __restrict__ cls,
                                                   const float* __restrict__ anchors,
                                                   const float* __restrict__ reg,
                                                   float4* __restrict__ out4,
                                                   int split4) {
    __shared__ int s_chunk;
    int t = blockIdx.x * blockDim.x + threadIdx.x;
    int stride = GPREP * 256;
    int sub = (blockIdx.x * 8 + (threadIdx.x >> 5)) & (NSUB - 1);

    // decode duty for the first AN threads
    if (t < AN) {
        int i = t;
        float a0 = anchors[i * 4 + 0], a1 = anchors[i * 4 + 1];
        float a2 = anchors[i * 4 + 2], a3 = anchors[i * 4 + 3];
        float r0 = reg[i * 4 + 0], r1 = reg[i * 4 + 1];
        float r2 = reg[i * 4 + 2], r3 = reg[i * 4 + 3];
        float aw = a2 - a0, ah = a3 - a1;
        float ax = a0 + 0.5f * aw, ay = a1 + 0.5f * ah;
        float cx = ax + r0 * 0.1f * aw;
        float cy = ay + r1 * 0.1f * ah;
        float w = aw * expf(r2 * 0.2f);
        float h = ah * expf(r3 * 0.2f);
        float x1 = fminf(fmaxf(cx - 0.5f * w, 0.0f), IMGF);
        float y1 = fminf(fmaxf(cy - 0.5f * h, 0.0f), IMGF);
        float x2 = fminf(fmaxf(cx + 0.5f * w, 0.0f), IMGF);
        float y2 = fminf(fmaxf(cy + 0.5f * h, 0.0f), IMGF);
        g_boxes[i * 4 + 0] = x1;
        g_boxes[i * 4 + 1] = y1;
        g_boxes[i * 4 + 2] = x2;
        g_boxes[i * 4 + 3] = y2;
        g_area[i] = (x2 - x1) * (y2 - y1);
    }

    // gather duty: 4 independent float4 loads (MLP), coalesced per iteration
    #pragma unroll
    for (int jj = 0; jj < 4; jj++) {
        int q = t + jj * stride;
        if (q < CA4) {
            float4 v = ((const float4*)cls)[q];
            float sv[4] = {v.x, v.y, v.z, v.w};
            #pragma unroll
            for (int k = 0; k < 4; k++) {
                float s = sv[k];
                if (s > T_C) {
                    int f = q * 4 + k;
                    int c = f % NC;
                    int a = f / NC;
                    int tier = (s > T_A) ? 0 : ((s > T_B) ? 1 : 2);
                    int p = atomicAdd(&g_cntp[sub][tier][c], 1);
                    if (p < SUBCAP)
                        g_cand[tier][c][sub * SUBCAP + p] =
                            ((unsigned long long)__float_as_uint(s) << 32) |
                            (unsigned long long)(0xFFFFFFFFu - (unsigned)a);
                }
            }
        }
    }

    // join fill-A via work-stealing cursor
    for (;;) {
        if (threadIdx.x == 0) s_chunk = atomicAdd(&g_fillcurA, 1);
        __syncthreads();
        int c0 = s_chunk * CH1;
        if (c0 >= split4) break;
        int end = min(c0 + CH1, split4);
        for (int i = c0 + threadIdx.x; i < end; i += 256) out4[i] = fill_val4(i);
        __syncthreads();
    }
}

// ---------------------------------------------------------------------------
// K3: flat scatter (1 thread per (class, slot)) + counter/cursor reset
// ---------------------------------------------------------------------------
__global__ void scatter_kernel(float* __restrict__ out) {
    int flat = blockIdx.x * blockDim.x + threadIdx.x;
    if (flat < NSUB * NTIER * NC) ((int*)g_cntp)[flat] = 0;
    if (flat == NSUB * NTIER * NC) { g_fillcurA = 0; g_fillcurB = 0; }
    if (flat >= NC * MAXKEEP) return;
    int c = flat / MAXKEEP;
    int t = flat - c * MAXKEEP;
    if (t >= g_kcnt[c]) return;
    int i = g_kidg[c][t];
    out[c * AN + i] = g_kscg[c][t];
    out[CA + c * AN + i] = (float)c;
    ((float4*)(out + 2 * CA))[c * AN + i] = g_kboxg[c][t];
    out[6 * CA + c * AN + i] = 1.0f;
}

// ---------------------------------------------------------------------------
// K2: blocks [0, NC) per-class NMS (then join fill); blocks [NC, NC+FILLB)
// fill [split4, n4) via work-stealing cursor.
// ---------------------------------------------------------------------------
__global__ __launch_bounds__(NT) void fused_kernel(const float* __restrict__ cls,
                                                   float4* __restrict__ out4,
                                                   int split4, int n4) {
    __shared__ int s_chunk;
    const int tid = threadIdx.x;
    const int lane = tid & 31, wid = tid >> 5;

    if (blockIdx.x < NC) {
        // ---------------- NMS path ----------------
        const int c = blockIdx.x;

        __shared__ unsigned long long skey[SKEYN];      // 16KB (fallback: supp bitmap)
        __shared__ unsigned long long cmask64[NB];
        __shared__ float4 bbox[NB];
        __shared__ float bar_[NB], bsc[NB];
        __shared__ int bidx[NB];
        __shared__ float4 kbox[MAXKEEP];
        __shared__ float kar[MAXKEEP], ksc[MAXKEEP];
        __shared__ int kid[MAXKEEP];
        __shared__ unsigned confParts[32];
        __shared__ unsigned long long km64_s;
        __shared__ unsigned long long red32[32];
        __shared__ int kcount;
        __shared__ int s_cnts[NTIER][NSUB];

        unsigned* cmW = (unsigned*)cmask64;

        // preload all 96 sub-counts in one parallel burst
        if (tid < NSUB * NTIER) {
            int s2 = tid / NTIER, tr = tid - s2 * NTIER;
            s_cnts[tr][s2] = g_cntp[s2][tr][c];
        }
        if (tid == 0) kcount = 0;
        __syncthreads();

        bool ok = true;
        for (int tier = 0; tier < NTIER; tier++) {
            if (kcount >= MAXKEEP) break;

            // concatenate the 32 sub-lists (counts in shared; loads pipeline)
            int n = 0;
            bool of = false;
            for (int s2 = 0; s2 < NSUB; s2++) {
                int cs = s_cnts[tier][s2];
                if (cs > SUBCAP) of = true;
                cs = min(cs, SUBCAP);
                for (int i = tid; i < cs; i += NT)
                    skey[min(n + i, SKEYN - 1)] = g_cand[tier][c][s2 * SUBCAP + i];
                n += cs;
            }
            if (of || n > SKEYN) { ok = false; break; }
            if (n == 0) continue;

            // ---- pad to m (>=64) + hybrid bitonic sort descending ----
            int m = 64;
            while (m < n) m <<= 1;
            for (int i = n + tid; i < m; i += NT) skey[i] = 0ULL;
            __syncthreads();

            // phase k=2..32 fully in registers (warp-local spans, no barriers)
            for (int span = wid; span < (m >> 5); span += 32) {
                int e = span * 32 + lane;
                unsigned long long v = skey[e];
                #pragma unroll
                for (int k = 2; k <= 32; k <<= 1) {
                    bool d = ((e & k) == 0);
                    #pragma unroll
                    for (int j = k >> 1; j >= 1; j >>= 1) {
                        unsigned long long vp = __shfl_xor_sync(FULLW, v, j);
                        bool takeMax = (((e & j) == 0) == d);
                        v = takeMax ? (v > vp ? v : vp) : (v < vp ? v : vp);
                    }
                }
                skey[e] = v;
            }
            __syncthreads();

            // phases k=64..m: shared steps for j>=32, fused shfl for j<=16
            for (int k = 64; k <= m; k <<= 1) {
                for (int j = k >> 1; j >= 32; j >>= 1) {
                    for (int i = tid; i < m; i += NT) {
                        int ixj = i ^ j;
                        if (ixj > i) {
                            bool desc = ((i & k) == 0);
                            unsigned long long A = skey[i], B2 = skey[ixj];
                            if (desc ? (A < B2) : (A > B2)) { skey[i] = B2; skey[ixj] = A; }
                        }
                    }
                    __syncthreads();
                }
                for (int span = wid; span < (m >> 5); span += 32) {
                    int e = span * 32 + lane;
                    unsigned long long v = skey[e];
                    bool d = ((e & k) == 0);
                    #pragma unroll
                    for (int j = 16; j >= 1; j >>= 1) {
                        unsigned long long vp = __shfl_xor_sync(FULLW, v, j);
                        bool takeMax = (((e & j) == 0) == d);
                        v = takeMax ? (v > vp ? v : vp) : (v < vp ? v : vp);
                    }
                    skey[e] = v;
                }
                __syncthreads();
            }

            // ---- batched walk, NB=64, 4 barriers/batch ----
            for (int base = 0; base < n; base += NB) {
                if (kcount >= MAXKEEP) break;
                int nb = min(NB, n - base);

                if (tid < nb) {
                    unsigned long long key = skey[base + tid];
                    float s = __uint_as_float((unsigned)(key >> 32));
                    int idx = (int)(0xFFFFFFFFu - (unsigned)key);
                    float4 bb;
                    bb.x = g_boxes[idx * 4 + 0];
                    bb.y = g_boxes[idx * 4 + 1];
                    bb.z = g_boxes[idx * 4 + 2];
                    bb.w = g_boxes[idx * 4 + 3];
                    bbox[tid] = bb;
                    bar_[tid] = g_area[idx];
                    bsc[tid] = s;
                    bidx[tid] = idx;
                }
                __syncthreads();  // B1

                int i = tid & 63;
                int g = tid >> 6;  // 0..15
                bool have = i < nb;
                float4 mb = make_float4(0, 0, 0, 0);
                float ma = 0;
                if (have) { mb = bbox[i]; ma = bar_[i]; }

                // phase 1a: conflict vs kept list, 16-way split per candidate
                int kc = kcount;
                bool cfk = false;
                if (have) {
                    for (int j = g; j < kc; j += 16) {
                        float4 kb = kbox[j];
                        float ix1 = fmaxf(kb.x, mb.x), iy1 = fmaxf(kb.y, mb.y);
                        float ix2 = fminf(kb.z, mb.z), iy2 = fminf(kb.w, mb.w);
                        float inter = fmaxf(ix2 - ix1, 0.0f) * fmaxf(iy2 - iy1, 0.0f);
                        if (inter > 0.0f) {
                            float iou = inter / ((kar[j] + ma) - inter);
                            if (iou > 0.5f) { cfk = true; break; }
                        }
                    }
                }
                unsigned cb = __ballot_sync(FULLW, cfk);
                if (lane == 0) confParts[wid] = cb;

                // phase 1b immediately (needs only bbox, synced at B1)
                for (int jb = 0; jb < nb; jb += 16) {
                    int j = jb + g;
                    bool cf = false;
                    if (have && j < nb && i != j) {
                        float4 jb4 = bbox[j];
                        float ja = bar_[j];
                        float ix1 = fmaxf(jb4.x, mb.x), iy1 = fmaxf(jb4.y, mb.y);
                        float ix2 = fminf(jb4.z, mb.z), iy2 = fminf(jb4.w, mb.w);
                        float inter = fmaxf(ix2 - ix1, 0.0f) * fmaxf(iy2 - iy1, 0.0f);
                        if (inter > 0.0f) {
                            float iou = inter / ((ja + ma) - inter);
                            cf = iou > 0.5f;
                        }
                    }
                    unsigned bits = __ballot_sync(FULLW, cf);
                    if (lane == 0 && j < nb) cmW[2 * j + (wid & 1)] = bits;
                }
                __syncthreads();  // B2 (confParts + cmask ready)

                // warp 0: alive + classify + resolve + truncate
                if (wid == 0) {
                    unsigned v = confParts[lane];
                    unsigned evenOr = __reduce_or_sync(FULLW, (lane & 1) ? 0u : v);
                    unsigned oddOr = __reduce_or_sync(FULLW, (lane & 1) ? v : 0u);
                    unsigned long long conf = ((unsigned long long)oddOr << 32) | evenOr;
                    unsigned long long hv = (nb >= 64) ? ~0ULL : ((1ULL << nb) - 1ULL);
                    unsigned long long alive64 = hv & ~conf;

                    // classify cands lane and lane+32
                    int q0 = lane, q1 = lane + 32;
                    bool a0v = (alive64 >> q0) & 1ULL;
                    bool a1v = (alive64 >> q1) & 1ULL;
                    unsigned long long r0 = a0v ? cmask64[q0] : 0ULL;
                    unsigned long long r1 = a1v ? cmask64[q1] : 0ULL;
                    bool t0b = a0v && ((r0 & alive64 & ((1ULL << q0) - 1ULL)) == 0ULL);
                    bool t1b = a1v && ((r1 & alive64 & ((1ULL << q1) - 1ULL)) == 0ULL);
                    bool d0b = a0v && !t0b;
                    bool d1b = a1v && !t1b;
                    unsigned bt0 = __ballot_sync(FULLW, t0b);
                    unsigned bt1 = __ballot_sync(FULLW, t1b);
                    unsigned bd0 = __ballot_sync(FULLW, d0b);
                    unsigned bd1 = __ballot_sync(FULLW, d1b);
                    if (lane == 0) {
                        unsigned long long kw = ((unsigned long long)bt1 << 32) | bt0;
                        unsigned long long dbits = ((unsigned long long)bd1 << 32) | bd0;
                        while (dbits) {
                            int q = __ffsll((long long)dbits) - 1;
                            dbits &= dbits - 1ULL;
                            unsigned long long below = (1ULL << q) - 1ULL;
                            if ((cmask64[q] & kw & below) == 0ULL) kw |= (1ULL << q);
                        }
                        int rem = MAXKEEP - kc;
                        int p = __popcll(kw);
                        while (p > rem) {
                            kw &= ~(0x8000000000000000ULL >> __clzll((long long)kw));
                            p--;
                        }
                        km64_s = kw;
                    }
                }
                __syncthreads();  // B3

                unsigned long long kw = km64_s;
                int kc0 = kcount;
                if (tid < 64 && ((kw >> tid) & 1ULL)) {
                    int pos = kc0 + __popcll(kw & ((1ULL << tid) - 1ULL));
                    kbox[pos] = bbox[tid];
                    kar[pos] = bar_[tid];
                    ksc[pos] = bsc[tid];
                    kid[pos] = bidx[tid];
                }
                if (tid == 0) kcount = kc0 + __popcll(kw);
                __syncthreads();  // B4
            }
        }
        __syncthreads();

        // ---- Exact fallback (never triggered for this data) ----
        if (!ok || kcount < MAXKEEP) {
            unsigned* supp = (unsigned*)skey;
            const int NW = (AN + 31) / 32;
            for (int w2 = tid; w2 < NW; w2 += NT) supp[w2] = 0u;
            if (tid == 0) kcount = 0;
            __syncthreads();
            for (int it = 0; it < MAXKEEP; it++) {
                unsigned long long best = 0ULL;
                for (int i = tid; i < AN; i += NT) {
                    if (!((supp[i >> 5] >> (i & 31)) & 1u)) {
                        float s = cls[i * NC + c];
                        if (s > 0.1f) {
                            unsigned long long k =
                                ((unsigned long long)__float_as_uint(s) << 32) |
                                (unsigned long long)(0xFFFFFFFFu - (unsigned)i);
                            if (k > best) best = k;
                        }
                    }
                }
                #pragma unroll
                for (int off = 16; off > 0; off >>= 1) {
                    unsigned long long o = __shfl_down_sync(FULLW, best, off);
                    if (o > best) best = o;
                }
                if (lane == 0) red32[wid] = best;
                __syncthreads();
                if (tid == 0) {
                    unsigned long long b2 = red32[0];
                    for (int w = 1; w < 32; w++)
                        if (red32[w] > b2) b2 = red32[w];
                    red32[0] = b2;
                }
                __syncthreads();
                unsigned long long bk = red32[0];
                __syncthreads();
                if (bk == 0ULL) break;
                int bi = (int)(0xFFFFFFFFu - (unsigned)bk);
                float s = __uint_as_float((unsigned)(bk >> 32));
                float zx1 = g_boxes[bi * 4 + 0], zy1 = g_boxes[bi * 4 + 1];
                float zx2 = g_boxes[bi * 4 + 2], zy2 = g_boxes[bi * 4 + 3];
                float za = g_area[bi];
                if (tid == 0) {
                    int kc2 = kcount;
                    kbox[kc2] = make_float4(zx1, zy1, zx2, zy2);
                    kar[kc2] = za; ksc[kc2] = s; kid[kc2] = bi;
                    kcount = kc2 + 1;
                }
                for (int i = tid; i < AN; i += NT) {
                    float ix1 = fmaxf(zx1, g_boxes[i * 4 + 0]);
                    float iy1 = fmaxf(zy1, g_boxes[i * 4 + 1]);
                    float ix2 = fminf(zx2, g_boxes[i * 4 + 2]);
                    float iy2 = fminf(zy2, g_boxes[i * 4 + 3]);
                    float inter = fmaxf(ix2 - ix1, 0.0f) * fmaxf(iy2 - iy1, 0.0f);
                    float iou = inter / ((za + g_area[i]) - inter);
                    if (iou > 0.5f || i == bi) atomicOr(&supp[i >> 5], 1u << (i & 31));
                }
                __syncthreads();
            }
            __syncthreads();
        }

        // ---- write compact results ----
        int kc = kcount;
        if (tid == 0) g_kcnt[c] = kc;
        for (int t = tid; t < kc; t += NT) {
            g_kboxg[c][t] = kbox[t];
            g_kscg[c][t] = ksc[t];
            g_kidg[c][t] = kid[t];
        }
        // fall through: join fill-B below
    }

    // ---------------- fill-B (work-stealing; fill blocks + post-NMS blocks) --
    for (;;) {
        if (tid == 0) s_chunk = atomicAdd(&g_fillcurB, 1);
        __syncthreads();
        int c0 = split4 + s_chunk * CH2;
        if (c0 >= n4) break;
        int end = min(c0 + CH2, n4);
        for (int i = c0 + tid; i < end; i += NT) out4[i] = fill_val4(i);
        __syncthreads();
    }
}

// ---------------------------------------------------------------------------
extern "C" void kernel_launch(void* const* d_in, const int* in_sizes, int n_in,
                              void* d_out, int out_size) {
    const float* classification = (const float*)d_in[0];  // [1, A, C]
    const float* regression = (const float*)d_in[1];      // [1, A, 4]
    const float* anchors = (const float*)d_in[2];         // [A, 4]
    float* out = (float*)d_out;

    int n4 = out_size / 4;
    int split4 = (int)(((long long)n4 * 3) / 10);  // 30% of fill in K1

    prep_kernel<<<GPREP, 256>>>(classification, anchors, regression,
                                (float4*)out, split4);
    fused_kernel<<<NC + FILLB, NT>>>(classification, (float4*)out, split4, n4);
    scatter_kernel<<<(NC * MAXKEEP + 255) / 256, 256>>>(out);
}